// round 1
// baseline (speedup 1.0000x reference)
#include <cuda_runtime.h>
#include <math.h>

#define BATCH 16
#define H 512
#define L 2048
#define N2 32
#define PI_F 3.14159265358979f

// ---------------- scratch (device globals; no allocations allowed) ----------
__device__ float4 g_modes[H * N2];                 // (wr, wi, ctr, cti) per (h,n)
__device__ float  g_y [BATCH * H * L];             // post-conv+gelu activations (64MB)
__device__ float  g_y2[BATCH * H * 2 * H];         // post-GEMM1 tanh activations (32MB)

// ---------------- kernel 0: per-(h,n) mode constants ------------------------
__global__ void setup_modes(const float* __restrict__ log_dt,
                            const float* __restrict__ C_re,
                            const float* __restrict__ C_im,
                            float4* __restrict__ modes) {
    int idx = blockIdx.x * blockDim.x + threadIdx.x;
    if (idx >= H * N2) return;
    int h = idx >> 5;
    int n = idx & 31;
    float dt = expf(log_dt[h]);
    // A = -0.5 + i*pi*n ; dtA = dt*A
    float Are = -0.5f, Aim = PI_F * (float)n;
    float ew = expf(-0.5f * dt);
    float s, c;
    sincosf(Aim * dt, &s, &c);
    float wr = ew * c, wi = ew * s;          // w = exp(dtA)
    // g = (w-1)/A = (w-1)*conj(A)/|A|^2
    float inv = 1.0f / (Are * Are + Aim * Aim);
    float xr = wr - 1.0f, xi = wi;
    float gr = (xr * Are + xi * Aim) * inv;
    float gi = (xi * Are - xr * Aim) * inv;
    float cr = C_re[idx], ci = C_im[idx];
    // fold the 2x of "2*Re(...)" into ct
    float ctr = 2.0f * (cr * gr - ci * gi);
    float cti = 2.0f * (cr * gi + ci * gr);
    modes[idx] = make_float4(wr, wi, ctr, cti);
}

// ---------------- kernel 1: fused scan-conv + D skip + exact GELU ----------
// One warp per (b,h) row; lane n owns complex mode n.
// s[l] = w*s[l-1] + u[l];  y[l] = Re sum_n ct_n * s_n[l]  (== causal conv u*k)
__global__ void __launch_bounds__(256) conv_scan(const float* __restrict__ u,
                                                 const float* __restrict__ D,
                                                 const float4* __restrict__ modes,
                                                 float* __restrict__ y) {
    int gwarp = (blockIdx.x * blockDim.x + threadIdx.x) >> 5;
    int lane  = threadIdx.x & 31;
    if (gwarp >= BATCH * H) return;
    int h = gwarp & (H - 1);

    float4 md = modes[(h << 5) + lane];       // wr, wi, ctr, cti
    float Dh  = D[h];

    const float* ur = u + (size_t)gwarp * L;
    float*       yr = y + (size_t)gwarp * L;

    float sr = 0.0f, si = 0.0f;
    for (int base = 0; base < L; base += 32) {
        float ubuf = ur[base + lane];         // coalesced 32-wide stage
        float yreg = 0.0f;
#pragma unroll
        for (int i = 0; i < 32; i++) {
            float uv  = __shfl_sync(0xffffffffu, ubuf, i);
            float nsr = fmaf(md.x, sr, fmaf(-md.y, si, uv));
            float nsi = fmaf(md.x, si, md.y * sr);
            sr = nsr; si = nsi;
            float v = fmaf(md.z, sr, -md.w * si);   // ctr*sr - cti*si
            v += __shfl_xor_sync(0xffffffffu, v, 1);
            v += __shfl_xor_sync(0xffffffffu, v, 2);
            v += __shfl_xor_sync(0xffffffffu, v, 4);
            v += __shfl_xor_sync(0xffffffffu, v, 8);
            v += __shfl_xor_sync(0xffffffffu, v, 16);
            if (i == lane) yreg = v;
        }
        float x = fmaf(Dh, ubuf, yreg);
        float g = 0.5f * x * (1.0f + erff(x * 0.70710678118654752f));
        yr[base + lane] = g;
    }
}

// ---------------- kernel 2/3: fp32 SIMT GEMM + bias (+tanh) ----------------
// C[M,N] = act(A[M,K] @ B[K,N] + bias[N]); BM=128, BN=64, BK=16; 256 thr; 8x4/thr.
// All dims divide the tiles exactly for both GEMMs (no bounds checks).
template <int ACT>  // 0: tanh, 1: identity
__global__ void __launch_bounds__(256) gemm_bias_act(const float* __restrict__ A,
                                                     const float* __restrict__ Bm,
                                                     const float* __restrict__ bias,
                                                     float* __restrict__ C,
                                                     int M, int N, int K) {
    __shared__ float As[16][128];
    __shared__ float Bs[16][64];
    int tid = threadIdx.x;
    int bm = blockIdx.y * 128;
    int bn = blockIdx.x * 64;
    int tx = tid & 15;       // N direction: 16 threads * 4 cols
    int ty = tid >> 4;       // M direction: 16 threads * 8 rows

    float acc[8][4];
#pragma unroll
    for (int i = 0; i < 8; i++)
#pragma unroll
        for (int j = 0; j < 4; j++) acc[i][j] = 0.0f;

    int arow0 = tid >> 2;    // 0..63
    int aquad = tid & 3;     // 0..3
    int brow  = tid >> 4;    // 0..15
    int bquad = tid & 15;    // 0..15

    for (int k0 = 0; k0 < K; k0 += 16) {
        // A tile (128 x 16), transposed into As[k][m]
#pragma unroll
        for (int i = 0; i < 2; i++) {
            int row = arow0 + i * 64;
            float4 av = *(const float4*)&A[(size_t)(bm + row) * K + k0 + aquad * 4];
            As[aquad * 4 + 0][row] = av.x;
            As[aquad * 4 + 1][row] = av.y;
            As[aquad * 4 + 2][row] = av.z;
            As[aquad * 4 + 3][row] = av.w;
        }
        // B tile (16 x 64)
        float4 bv = *(const float4*)&Bm[(size_t)(k0 + brow) * N + bn + bquad * 4];
        *(float4*)&Bs[brow][bquad * 4] = bv;
        __syncthreads();

#pragma unroll
        for (int kk = 0; kk < 16; kk++) {
            float4 a0 = *(const float4*)&As[kk][ty * 8];
            float4 a1 = *(const float4*)&As[kk][ty * 8 + 4];
            float4 b  = *(const float4*)&Bs[kk][tx * 4];
            float ar[8] = {a0.x, a0.y, a0.z, a0.w, a1.x, a1.y, a1.z, a1.w};
            float br[4] = {b.x, b.y, b.z, b.w};
#pragma unroll
            for (int i = 0; i < 8; i++)
#pragma unroll
                for (int j = 0; j < 4; j++)
                    acc[i][j] = fmaf(ar[i], br[j], acc[i][j]);
        }
        __syncthreads();
    }

    float bb[4];
#pragma unroll
    for (int j = 0; j < 4; j++) bb[j] = bias[bn + tx * 4 + j];

#pragma unroll
    for (int i = 0; i < 8; i++) {
        float4 outv;
        float* ov = (float*)&outv;
#pragma unroll
        for (int j = 0; j < 4; j++) {
            float v = acc[i][j] + bb[j];
            if (ACT == 0) v = tanhf(v);
            ov[j] = v;
        }
        *(float4*)&C[(size_t)(bm + ty * 8 + i) * N + bn + tx * 4] = outv;
    }
}

// ---------------- launch ----------------------------------------------------
extern "C" void kernel_launch(void* const* d_in, const int* in_sizes, int n_in,
                              void* d_out, int out_size) {
    const float* u      = (const float*)d_in[0];
    const float* D      = (const float*)d_in[1];
    const float* log_dt = (const float*)d_in[2];
    const float* C_re   = (const float*)d_in[3];
    const float* C_im   = (const float*)d_in[4];
    const float* W1     = (const float*)d_in[5];
    const float* b1     = (const float*)d_in[6];
    const float* W2     = (const float*)d_in[7];
    const float* b2     = (const float*)d_in[8];
    float* out = (float*)d_out;

    float4* modes_p; float* y_p; float* y2_p;
    cudaGetSymbolAddress((void**)&modes_p, g_modes);
    cudaGetSymbolAddress((void**)&y_p,     g_y);
    cudaGetSymbolAddress((void**)&y2_p,    g_y2);

    // 0) mode constants: H*N2 = 16384 threads
    setup_modes<<<64, 256>>>(log_dt, C_re, C_im, modes_p);

    // 1) fused conv scan + D + gelu: 8192 warps
    conv_scan<<<(BATCH * H * 32) / 256, 256>>>(u, D, modes_p, y_p);

    // 2) GEMM1: (8192 x 2048) @ (2048 x 1024), +b1, tanh
    gemm_bias_act<0><<<dim3(1024 / 64, 8192 / 128), 256>>>(y_p, W1, b1, y2_p,
                                                           BATCH * H, 2 * H, L);

    // 3) GEMM2: (8192 x 1024) @ (1024 x 512), +b2
    gemm_bias_act<1><<<dim3(512 / 64, 8192 / 128), 256>>>(y2_p, W2, b2, out,
                                                          BATCH * H, H, 2 * H);
}

// round 4
// speedup vs baseline: 1.9197x; 1.9197x over previous
#include <cuda_runtime.h>
#include <cuda_bf16.h>
#include <math.h>
#include <stdint.h>

#define BATCH 16
#define H 512
#define L 2048
#define N2 32
#define PI_F 3.14159265358979f

#define M_TOTAL (BATCH * H)      // 8192
#define TM 128
#define TN 128
#define BK 64

// ---------------- scratch (device globals; no allocations allowed) ----------
__device__ float4 g_modes[H * N2];
__device__ __align__(128) __nv_bfloat16 g_yh[M_TOTAL * L];
__device__ __align__(128) __nv_bfloat16 g_yl[M_TOTAL * L];
__device__ __align__(128) __nv_bfloat16 g_w1h[2 * H * L];      // W1^T [1024 x 2048]
__device__ __align__(128) __nv_bfloat16 g_w1l[2 * H * L];
__device__ __align__(128) __nv_bfloat16 g_w2h[H * 2 * H];      // W2^T [512 x 1024]
__device__ __align__(128) __nv_bfloat16 g_w2l[H * 2 * H];
__device__ __align__(128) __nv_bfloat16 g_y2h[M_TOTAL * 2 * H];
__device__ __align__(128) __nv_bfloat16 g_y2l[M_TOTAL * 2 * H];

// ---------------- helpers ----------------------------------------------------
__device__ __forceinline__ uint32_t smem_u32(const void* p) {
    uint32_t a;
    asm("{ .reg .u64 t; cvta.to.shared.u64 t, %1; cvt.u32.u64 %0, t; }"
        : "=r"(a) : "l"(p));
    return a;
}
__device__ __forceinline__ void ldsm4(uint32_t addr, uint32_t& r0, uint32_t& r1,
                                      uint32_t& r2, uint32_t& r3) {
    asm volatile("ldmatrix.sync.aligned.m8n8.x4.shared.b16 {%0,%1,%2,%3}, [%4];"
                 : "=r"(r0), "=r"(r1), "=r"(r2), "=r"(r3) : "r"(addr));
}
__device__ __forceinline__ void mma16816(float c[4], uint32_t a0, uint32_t a1,
                                         uint32_t a2, uint32_t a3,
                                         uint32_t b0, uint32_t b1) {
    asm volatile("mma.sync.aligned.m16n8k16.row.col.f32.bf16.bf16.f32 "
                 "{%0,%1,%2,%3}, {%4,%5,%6,%7}, {%8,%9}, {%0,%1,%2,%3};"
                 : "+f"(c[0]), "+f"(c[1]), "+f"(c[2]), "+f"(c[3])
                 : "r"(a0), "r"(a1), "r"(a2), "r"(a3), "r"(b0), "r"(b1));
}
#define CP_COMMIT() asm volatile("cp.async.commit_group;" ::: "memory")
#define CP_WAIT(n)  asm volatile("cp.async.wait_group %0;" :: "n"(n) : "memory")

// ---------------- kernel 0: per-(h,n) mode constants ------------------------
__global__ void setup_modes(const float* __restrict__ log_dt,
                            const float* __restrict__ C_re,
                            const float* __restrict__ C_im,
                            float4* __restrict__ modes) {
    int idx = blockIdx.x * blockDim.x + threadIdx.x;
    if (idx >= H * N2) return;
    int h = idx >> 5;
    int n = idx & 31;
    float dt = expf(log_dt[h]);
    float Are = -0.5f, Aim = PI_F * (float)n;
    float ew = expf(-0.5f * dt);
    float s, c;
    sincosf(Aim * dt, &s, &c);
    float wr = ew * c, wi = ew * s;
    float inv = 1.0f / (Are * Are + Aim * Aim);
    float xr = wr - 1.0f, xi = wi;
    float gr = (xr * Are + xi * Aim) * inv;
    float gi = (xi * Are - xr * Aim) * inv;
    float cr = C_re[idx], ci = C_im[idx];
    float ctr = 2.0f * (cr * gr - ci * gi);
    float cti = 2.0f * (cr * gi + ci * gr);
    modes[idx] = make_float4(wr, wi, ctr, cti);
}

// ---------------- kernel 1: fused scan-conv + D skip + GELU + bf16-split ---
__global__ void __launch_bounds__(256) conv_scan(const float* __restrict__ u,
                                                 const float* __restrict__ D,
                                                 const float4* __restrict__ modes,
                                                 __nv_bfloat16* __restrict__ yh,
                                                 __nv_bfloat16* __restrict__ yl) {
    int gwarp = (blockIdx.x * blockDim.x + threadIdx.x) >> 5;
    int lane  = threadIdx.x & 31;
    if (gwarp >= BATCH * H) return;
    int h = gwarp & (H - 1);

    float4 md = modes[(h << 5) + lane];
    float Dh  = D[h];

    const float* ur = u + (size_t)gwarp * L;
    __nv_bfloat16* yhr = yh + (size_t)gwarp * L;
    __nv_bfloat16* ylr = yl + (size_t)gwarp * L;

    float sr = 0.0f, si = 0.0f;
    for (int base = 0; base < L; base += 32) {
        float ubuf = ur[base + lane];
        float yreg = 0.0f;
#pragma unroll
        for (int i = 0; i < 32; i++) {
            float uv  = __shfl_sync(0xffffffffu, ubuf, i);
            float nsr = fmaf(md.x, sr, fmaf(-md.y, si, uv));
            float nsi = fmaf(md.x, si, md.y * sr);
            sr = nsr; si = nsi;
            float v = fmaf(md.z, sr, -md.w * si);
            v += __shfl_xor_sync(0xffffffffu, v, 1);
            v += __shfl_xor_sync(0xffffffffu, v, 2);
            v += __shfl_xor_sync(0xffffffffu, v, 4);
            v += __shfl_xor_sync(0xffffffffu, v, 8);
            v += __shfl_xor_sync(0xffffffffu, v, 16);
            if (i == lane) yreg = v;
        }
        float x = fmaf(Dh, ubuf, yreg);
        float g = 0.5f * x * (1.0f + erff(x * 0.70710678118654752f));
        __nv_bfloat16 hi = __float2bfloat16_rn(g);
        __nv_bfloat16 lo = __float2bfloat16_rn(g - __bfloat162float(hi));
        yhr[base + lane] = hi;
        ylr[base + lane] = lo;
    }
}

// ---------------- kernel 2: transpose + bf16 split for weights -------------
__global__ void __launch_bounds__(256) transpose_split(const float* __restrict__ src,
                                                       __nv_bfloat16* __restrict__ dh,
                                                       __nv_bfloat16* __restrict__ dl,
                                                       int R, int C) {
    __shared__ float t[32][33];
    int c0 = blockIdx.x * 32, r0 = blockIdx.y * 32;
    int tx = threadIdx.x, ty = threadIdx.y;   // block (32, 8)
#pragma unroll
    for (int i = 0; i < 4; i++)
        t[ty + 8 * i][tx] = src[(size_t)(r0 + ty + 8 * i) * C + c0 + tx];
    __syncthreads();
#pragma unroll
    for (int i = 0; i < 4; i++) {
        float v = t[tx][ty + 8 * i];
        __nv_bfloat16 hi = __float2bfloat16_rn(v);
        __nv_bfloat16 lo = __float2bfloat16_rn(v - __bfloat162float(hi));
        size_t o = (size_t)(c0 + ty + 8 * i) * R + r0 + tx;
        dh[o] = hi;
        dl[o] = lo;
    }
}

// ---------------- kernel 3/4: mma.sync bf16-split GEMM ----------------------
// C[M,N] = act(A[M,K] @ B[N,K]^T + bias);  A,B as bf16 hi/lo pairs.
// CTA tile 128x128, BK=64, 2-stage cp.async pipeline, warps 4(m) x 2(n).
// smem tile layout: 128 rows x 128B, 16B units XOR-swizzled by (row&7).
#define ST_TILE (TM * 128)                // 16384 B per tile
#define STAGE   (4 * ST_TILE)             // Ah, Al, Bh, Bl = 65536 B
#define GEMM_SMEM (2 * STAGE)             // 131072 B

__device__ __forceinline__ void load_tile_ca(const __nv_bfloat16* __restrict__ g,
                                             int K, int k0, uint32_t sbase, int tid) {
#pragma unroll
    for (int it = 0; it < 4; it++) {
        int idx = it * 256 + tid;
        int row = idx >> 3, unit = idx & 7;
        const void* src = g + (size_t)row * K + k0 + unit * 8;
        uint32_t dst = sbase + row * 128 + ((unit ^ (row & 7)) << 4);
        asm volatile("cp.async.cg.shared.global [%0], [%1], 16;"
                     :: "r"(dst), "l"(src) : "memory");
    }
}

template <bool TANH, bool OUTBF>
__global__ void __launch_bounds__(256) gemm_mma(const __nv_bfloat16* __restrict__ Ah,
                                                const __nv_bfloat16* __restrict__ Al,
                                                const __nv_bfloat16* __restrict__ Bh,
                                                const __nv_bfloat16* __restrict__ Bl,
                                                const float* __restrict__ bias,
                                                float* __restrict__ outf,
                                                __nv_bfloat16* __restrict__ outh,
                                                __nv_bfloat16* __restrict__ outl,
                                                int M, int N, int K) {
    extern __shared__ char sm[];
    uint32_t sb = smem_u32(sm);
    int tid  = threadIdx.x;
    int lane = tid & 31;
    int warp = tid >> 5;
    int wm = warp & 3;            // 0..3 (m)
    int wn = warp >> 2;           // 0..1 (n)
    int bm = blockIdx.y * TM;
    int bn = blockIdx.x * TN;

    const __nv_bfloat16* A0h = Ah + (size_t)bm * K;
    const __nv_bfloat16* A0l = Al + (size_t)bm * K;
    const __nv_bfloat16* B0h = Bh + (size_t)bn * K;
    const __nv_bfloat16* B0l = Bl + (size_t)bn * K;

    float acc[2][8][4];
#pragma unroll
    for (int i = 0; i < 2; i++)
#pragma unroll
        for (int j = 0; j < 8; j++)
#pragma unroll
            for (int q = 0; q < 4; q++) acc[i][j][q] = 0.0f;

    // per-lane fragment address precompute
    int a_row  = wm * 32 + (lane & 15);            // +16*i keeps row&7
    int a_sw   = a_row & 7;
    uint32_t a_off = (uint32_t)a_row * 128;
    int a_kbit = lane >> 4;                         // 0/1
    int b_row  = wn * 64 + (lane & 7) + ((lane & 16) ? 8 : 0);  // +16*j keeps row&7
    int b_sw   = b_row & 7;
    uint32_t b_off = (uint32_t)b_row * 128;
    int b_kbit = (lane & 8) ? 1 : 0;

    int NC = K / BK;
    // prologue: stages 0 and 1
    {
        load_tile_ca(A0h, K, 0, sb + 0 * ST_TILE, tid);
        load_tile_ca(A0l, K, 0, sb + 1 * ST_TILE, tid);
        load_tile_ca(B0h, K, 0, sb + 2 * ST_TILE, tid);
        load_tile_ca(B0l, K, 0, sb + 3 * ST_TILE, tid);
        CP_COMMIT();
        load_tile_ca(A0h, K, BK, sb + STAGE + 0 * ST_TILE, tid);
        load_tile_ca(A0l, K, BK, sb + STAGE + 1 * ST_TILE, tid);
        load_tile_ca(B0h, K, BK, sb + STAGE + 2 * ST_TILE, tid);
        load_tile_ca(B0l, K, BK, sb + STAGE + 3 * ST_TILE, tid);
        CP_COMMIT();
    }

    for (int c = 0; c < NC; c++) {
        if (c + 1 < NC) { CP_WAIT(1); } else { CP_WAIT(0); }
        __syncthreads();
        uint32_t base = sb + (uint32_t)(c & 1) * STAGE;
        uint32_t bAh = base + 0 * ST_TILE + a_off;
        uint32_t bAl = base + 1 * ST_TILE + a_off;
        uint32_t bBh = base + 2 * ST_TILE + b_off;
        uint32_t bBl = base + 3 * ST_TILE + b_off;

#pragma unroll
        for (int kk = 0; kk < 4; kk++) {
            uint32_t aun = (uint32_t)(((kk * 2 + a_kbit) ^ a_sw) << 4);
            uint32_t bun = (uint32_t)(((kk * 2 + b_kbit) ^ b_sw) << 4);
            uint32_t ah[2][4], al[2][4];
#pragma unroll
            for (int i = 0; i < 2; i++) {
                ldsm4(bAh + i * 2048 + aun, ah[i][0], ah[i][1], ah[i][2], ah[i][3]);
                ldsm4(bAl + i * 2048 + aun, al[i][0], al[i][1], al[i][2], al[i][3]);
            }
            uint32_t bh[8][2], bl[8][2];
#pragma unroll
            for (int jp = 0; jp < 4; jp++) {
                ldsm4(bBh + jp * 2048 + bun, bh[2 * jp][0], bh[2 * jp][1],
                      bh[2 * jp + 1][0], bh[2 * jp + 1][1]);
                ldsm4(bBl + jp * 2048 + bun, bl[2 * jp][0], bl[2 * jp][1],
                      bl[2 * jp + 1][0], bl[2 * jp + 1][1]);
            }
#pragma unroll
            for (int i = 0; i < 2; i++)
#pragma unroll
                for (int j = 0; j < 8; j++) {
                    mma16816(acc[i][j], ah[i][0], ah[i][1], ah[i][2], ah[i][3],
                             bh[j][0], bh[j][1]);
                    mma16816(acc[i][j], ah[i][0], ah[i][1], ah[i][2], ah[i][3],
                             bl[j][0], bl[j][1]);
                    mma16816(acc[i][j], al[i][0], al[i][1], al[i][2], al[i][3],
                             bh[j][0], bh[j][1]);
                }
        }
        __syncthreads();
        if (c + 2 < NC) {
            uint32_t nb = sb + (uint32_t)(c & 1) * STAGE;
            int k0 = (c + 2) * BK;
            load_tile_ca(A0h, K, k0, nb + 0 * ST_TILE, tid);
            load_tile_ca(A0l, K, k0, nb + 1 * ST_TILE, tid);
            load_tile_ca(B0h, K, k0, nb + 2 * ST_TILE, tid);
            load_tile_ca(B0l, K, k0, nb + 3 * ST_TILE, tid);
            CP_COMMIT();
        }
    }

    // epilogue: acc[i][j][q] -> (r, c): q0:(r,c) q1:(r,c+1) q2:(r+8,c) q3:(r+8,c+1)
    int r0g = bm + wm * 32 + (lane >> 2);
    int c0g = bn + wn * 64 + 2 * (lane & 3);
#pragma unroll
    for (int i = 0; i < 2; i++) {
#pragma unroll
        for (int j = 0; j < 8; j++) {
            int r = r0g + i * 16;
            int cc = c0g + j * 8;
            float bz0 = bias[cc], bz1 = bias[cc + 1];
            float v0 = acc[i][j][0] + bz0;
            float v1 = acc[i][j][1] + bz1;
            float v2 = acc[i][j][2] + bz0;
            float v3 = acc[i][j][3] + bz1;
            if (TANH) { v0 = tanhf(v0); v1 = tanhf(v1); v2 = tanhf(v2); v3 = tanhf(v3); }
            if (OUTBF) {
                __nv_bfloat16 h0 = __float2bfloat16_rn(v0);
                __nv_bfloat16 h1 = __float2bfloat16_rn(v1);
                __nv_bfloat16 h2 = __float2bfloat16_rn(v2);
                __nv_bfloat16 h3 = __float2bfloat16_rn(v3);
                uint32_t ph01 = ((uint32_t)__bfloat16_as_ushort(h1) << 16) |
                                (uint32_t)__bfloat16_as_ushort(h0);
                uint32_t ph23 = ((uint32_t)__bfloat16_as_ushort(h3) << 16) |
                                (uint32_t)__bfloat16_as_ushort(h2);
                __nv_bfloat16 l0 = __float2bfloat16_rn(v0 - __bfloat162float(h0));
                __nv_bfloat16 l1 = __float2bfloat16_rn(v1 - __bfloat162float(h1));
                __nv_bfloat16 l2 = __float2bfloat16_rn(v2 - __bfloat162float(h2));
                __nv_bfloat16 l3 = __float2bfloat16_rn(v3 - __bfloat162float(h3));
                uint32_t pl01 = ((uint32_t)__bfloat16_as_ushort(l1) << 16) |
                                (uint32_t)__bfloat16_as_ushort(l0);
                uint32_t pl23 = ((uint32_t)__bfloat16_as_ushort(l3) << 16) |
                                (uint32_t)__bfloat16_as_ushort(l2);
                *(uint32_t*)(outh + (size_t)r * N + cc)       = ph01;
                *(uint32_t*)(outh + (size_t)(r + 8) * N + cc) = ph23;
                *(uint32_t*)(outl + (size_t)r * N + cc)       = pl01;
                *(uint32_t*)(outl + (size_t)(r + 8) * N + cc) = pl23;
            } else {
                *(float2*)(outf + (size_t)r * N + cc)       = make_float2(v0, v1);
                *(float2*)(outf + (size_t)(r + 8) * N + cc) = make_float2(v2, v3);
            }
        }
    }
}

// ---------------- launch ----------------------------------------------------
extern "C" void kernel_launch(void* const* d_in, const int* in_sizes, int n_in,
                              void* d_out, int out_size) {
    const float* u      = (const float*)d_in[0];
    const float* D      = (const float*)d_in[1];
    const float* log_dt = (const float*)d_in[2];
    const float* C_re   = (const float*)d_in[3];
    const float* C_im   = (const float*)d_in[4];
    const float* W1     = (const float*)d_in[5];
    const float* b1     = (const float*)d_in[6];
    const float* W2     = (const float*)d_in[7];
    const float* b2     = (const float*)d_in[8];
    float* out = (float*)d_out;

    float4* modes_p;
    __nv_bfloat16 *yh_p, *yl_p, *w1h_p, *w1l_p, *w2h_p, *w2l_p, *y2h_p, *y2l_p;
    cudaGetSymbolAddress((void**)&modes_p, g_modes);
    cudaGetSymbolAddress((void**)&yh_p,  g_yh);
    cudaGetSymbolAddress((void**)&yl_p,  g_yl);
    cudaGetSymbolAddress((void**)&w1h_p, g_w1h);
    cudaGetSymbolAddress((void**)&w1l_p, g_w1l);
    cudaGetSymbolAddress((void**)&w2h_p, g_w2h);
    cudaGetSymbolAddress((void**)&w2l_p, g_w2l);
    cudaGetSymbolAddress((void**)&y2h_p, g_y2h);
    cudaGetSymbolAddress((void**)&y2l_p, g_y2l);

    cudaFuncSetAttribute(gemm_mma<true, true>,
                         cudaFuncAttributeMaxDynamicSharedMemorySize, GEMM_SMEM);
    cudaFuncSetAttribute(gemm_mma<false, false>,
                         cudaFuncAttributeMaxDynamicSharedMemorySize, GEMM_SMEM);

    setup_modes<<<64, 256>>>(log_dt, C_re, C_im, modes_p);

    transpose_split<<<dim3(1024 / 32, 2048 / 32), dim3(32, 8)>>>(W1, w1h_p, w1l_p,
                                                                 L, 2 * H);
    transpose_split<<<dim3(512 / 32, 1024 / 32), dim3(32, 8)>>>(W2, w2h_p, w2l_p,
                                                                2 * H, H);

    conv_scan<<<(BATCH * H * 32) / 256, 256>>>(u, D, modes_p, yh_p, yl_p);

    // GEMM1: (8192 x 2048) @ (2048 x 1024) + b1, tanh -> bf16 hi/lo
    gemm_mma<true, true><<<dim3((2 * H) / TN, M_TOTAL / TM), 256, GEMM_SMEM>>>(
        yh_p, yl_p, w1h_p, w1l_p, b1, nullptr, y2h_p, y2l_p,
        M_TOTAL, 2 * H, L);

    // GEMM2: (8192 x 1024) @ (1024 x 512) + b2 -> fp32 out
    gemm_mma<false, false><<<dim3(H / TN, M_TOTAL / TM), 256, GEMM_SMEM>>>(
        y2h_p, y2l_p, w2h_p, w2l_p, b2, out, nullptr, nullptr,
        M_TOTAL, H, 2 * H);
}

// round 6
// speedup vs baseline: 2.3537x; 1.2261x over previous
#include <cuda_runtime.h>
#include <cuda_bf16.h>
#include <math.h>
#include <stdint.h>

#define BATCH 16
#define H 512
#define L 2048
#define N2 32
#define PI_F 3.14159265358979f

#define M_TOTAL (BATCH * H)      // 8192
#define TM 128
#define TN 128
#define BK 64

// ---------------- scratch (device globals; no allocations allowed) ----------
__device__ float4 g_modes[H * N2];
__device__ __align__(128) __nv_bfloat16 g_yh[M_TOTAL * L];
__device__ __align__(128) __nv_bfloat16 g_yl[M_TOTAL * L];
__device__ __align__(128) __nv_bfloat16 g_w1h[2 * H * L];      // W1^T [1024 x 2048]
__device__ __align__(128) __nv_bfloat16 g_w1l[2 * H * L];
__device__ __align__(128) __nv_bfloat16 g_w2h[H * 2 * H];      // W2^T [512 x 1024]
__device__ __align__(128) __nv_bfloat16 g_w2l[H * 2 * H];
__device__ __align__(128) __nv_bfloat16 g_y2h[M_TOTAL * 2 * H];
__device__ __align__(128) __nv_bfloat16 g_y2l[M_TOTAL * 2 * H];

// ---------------- helpers ----------------------------------------------------
__device__ __forceinline__ uint32_t smem_u32(const void* p) {
    uint32_t a;
    asm("{ .reg .u64 t; cvta.to.shared.u64 t, %1; cvt.u32.u64 %0, t; }"
        : "=r"(a) : "l"(p));
    return a;
}
__device__ __forceinline__ void ldsm4(uint32_t addr, uint32_t& r0, uint32_t& r1,
                                      uint32_t& r2, uint32_t& r3) {
    asm volatile("ldmatrix.sync.aligned.m8n8.x4.shared.b16 {%0,%1,%2,%3}, [%4];"
                 : "=r"(r0), "=r"(r1), "=r"(r2), "=r"(r3) : "r"(addr));
}
__device__ __forceinline__ void mma16816(float c[4], uint32_t a0, uint32_t a1,
                                         uint32_t a2, uint32_t a3,
                                         uint32_t b0, uint32_t b1) {
    asm volatile("mma.sync.aligned.m16n8k16.row.col.f32.bf16.bf16.f32 "
                 "{%0,%1,%2,%3}, {%4,%5,%6,%7}, {%8,%9}, {%0,%1,%2,%3};"
                 : "+f"(c[0]), "+f"(c[1]), "+f"(c[2]), "+f"(c[3])
                 : "r"(a0), "r"(a1), "r"(a2), "r"(a3), "r"(b0), "r"(b1));
}
#define CP_COMMIT() asm volatile("cp.async.commit_group;" ::: "memory")
#define CP_WAIT(n)  asm volatile("cp.async.wait_group %0;" :: "n"(n) : "memory")

// ---------------- kernel 0: per-(h,n) mode constants ------------------------
__global__ void setup_modes(const float* __restrict__ log_dt,
                            const float* __restrict__ C_re,
                            const float* __restrict__ C_im,
                            float4* __restrict__ modes) {
    int idx = blockIdx.x * blockDim.x + threadIdx.x;
    if (idx >= H * N2) return;
    int h = idx >> 5;
    int n = idx & 31;
    float dt = expf(log_dt[h]);
    float Are = -0.5f, Aim = PI_F * (float)n;
    float ew = expf(-0.5f * dt);
    float s, c;
    sincosf(Aim * dt, &s, &c);
    float wr = ew * c, wi = ew * s;
    float inv = 1.0f / (Are * Are + Aim * Aim);
    float xr = wr - 1.0f, xi = wi;
    float gr = (xr * Are + xi * Aim) * inv;
    float gi = (xi * Are - xr * Aim) * inv;
    float cr = C_re[idx], ci = C_im[idx];
    float ctr = 2.0f * (cr * gr - ci * gi);
    float cti = 2.0f * (cr * gi + ci * gr);
    modes[idx] = make_float4(wr, wi, ctr, cti);
}

// ---------------- kernel 1: fused scan-conv, 4 modes/lane, 8 lanes/row ------
// Subgroup of 8 lanes owns one (b,h) row; lane owns modes 4*sl..4*sl+3.
// Step i = 4j+k: u broadcast from lane j's float4; 3-stage xor reduce (width 8);
// lane j keeps y for its own 4 u positions -> register-local epilogue.
__global__ void __launch_bounds__(256) conv_scan(const float* __restrict__ u,
                                                 const float* __restrict__ D,
                                                 const float4* __restrict__ modes,
                                                 __nv_bfloat16* __restrict__ yh,
                                                 __nv_bfloat16* __restrict__ yl) {
    const uint32_t FULL = 0xffffffffu;
    int tid = blockIdx.x * blockDim.x + threadIdx.x;
    int sg  = tid >> 3;                 // row id = b*H + h
    if (sg >= BATCH * H) return;
    int sl  = threadIdx.x & 7;          // lane in 8-lane segment
    int h   = sg & (H - 1);

    float4 md[4];
#pragma unroll
    for (int c = 0; c < 4; c++) md[c] = modes[(h << 5) + sl * 4 + c];
    float Dh = D[h];

    const float4* ur4 = (const float4*)(u + (size_t)sg * L);
    __nv_bfloat16* yhr = yh + (size_t)sg * L;
    __nv_bfloat16* ylr = yl + (size_t)sg * L;

    float sr[4] = {0, 0, 0, 0}, si[4] = {0, 0, 0, 0};

    for (int base = 0; base < L; base += 32) {
        float4 u4 = ur4[(base >> 2) + sl];
        float uu[4] = {u4.x, u4.y, u4.z, u4.w};
        float yreg[4] = {0, 0, 0, 0};
#pragma unroll
        for (int i = 0; i < 32; i++) {
            const int j = i >> 2, k = i & 3;
            float uv = __shfl_sync(FULL, uu[k], j, 8);
            float v;
#pragma unroll
            for (int c = 0; c < 4; c++) {
                float nsr = fmaf(md[c].x, sr[c], fmaf(-md[c].y, si[c], uv));
                float nsi = fmaf(md[c].x, si[c], md[c].y * sr[c]);
                sr[c] = nsr; si[c] = nsi;
                float t = fmaf(md[c].z, sr[c], -md[c].w * si[c]);
                v = (c == 0) ? t : (v + t);
            }
            v += __shfl_xor_sync(FULL, v, 1, 8);
            v += __shfl_xor_sync(FULL, v, 2, 8);
            v += __shfl_xor_sync(FULL, v, 4, 8);
            if (j == sl) yreg[k] = v;
        }
        // epilogue: 4 consecutive outputs at base + 4*sl
        ushort hs[4], ls[4];
#pragma unroll
        for (int k = 0; k < 4; k++) {
            float x = fmaf(Dh, uu[k], yreg[k]);
            float g = 0.5f * x * (1.0f + erff(x * 0.70710678118654752f));
            __nv_bfloat16 hi = __float2bfloat16_rn(g);
            __nv_bfloat16 lo = __float2bfloat16_rn(g - __bfloat162float(hi));
            hs[k] = __bfloat16_as_ushort(hi);
            ls[k] = __bfloat16_as_ushort(lo);
        }
        uint2 ph, pl;
        ph.x = (uint32_t)hs[0] | ((uint32_t)hs[1] << 16);
        ph.y = (uint32_t)hs[2] | ((uint32_t)hs[3] << 16);
        pl.x = (uint32_t)ls[0] | ((uint32_t)ls[1] << 16);
        pl.y = (uint32_t)ls[2] | ((uint32_t)ls[3] << 16);
        *(uint2*)(yhr + base + 4 * sl) = ph;
        *(uint2*)(ylr + base + 4 * sl) = pl;
    }
}

// ---------------- kernel 2: transpose + bf16 split for weights -------------
__global__ void __launch_bounds__(256) transpose_split(const float* __restrict__ src,
                                                       __nv_bfloat16* __restrict__ dh,
                                                       __nv_bfloat16* __restrict__ dl,
                                                       int R, int C) {
    __shared__ float t[32][33];
    int c0 = blockIdx.x * 32, r0 = blockIdx.y * 32;
    int tx = threadIdx.x, ty = threadIdx.y;   // block (32, 8)
#pragma unroll
    for (int i = 0; i < 4; i++)
        t[ty + 8 * i][tx] = src[(size_t)(r0 + ty + 8 * i) * C + c0 + tx];
    __syncthreads();
#pragma unroll
    for (int i = 0; i < 4; i++) {
        float v = t[tx][ty + 8 * i];
        __nv_bfloat16 hi = __float2bfloat16_rn(v);
        __nv_bfloat16 lo = __float2bfloat16_rn(v - __bfloat162float(hi));
        size_t o = (size_t)(c0 + ty + 8 * i) * R + r0 + tx;
        dh[o] = hi;
        dl[o] = lo;
    }
}

// ---------------- kernel 3/4: mma.sync bf16-split GEMM ----------------------
#define ST_TILE (TM * 128)                // 16384 B per tile
#define STAGE   (4 * ST_TILE)             // Ah, Al, Bh, Bl = 65536 B
#define GEMM_SMEM (2 * STAGE)             // 131072 B

__device__ __forceinline__ void load_tile_ca(const __nv_bfloat16* __restrict__ g,
                                             int K, int k0, uint32_t sbase, int tid) {
#pragma unroll
    for (int it = 0; it < 4; it++) {
        int idx = it * 256 + tid;
        int row = idx >> 3, unit = idx & 7;
        const void* src = g + (size_t)row * K + k0 + unit * 8;
        uint32_t dst = sbase + row * 128 + ((unit ^ (row & 7)) << 4);
        asm volatile("cp.async.cg.shared.global [%0], [%1], 16;"
                     :: "r"(dst), "l"(src) : "memory");
    }
}

template <bool TANH, bool OUTBF>
__global__ void __launch_bounds__(256) gemm_mma(const __nv_bfloat16* __restrict__ Ah,
                                                const __nv_bfloat16* __restrict__ Al,
                                                const __nv_bfloat16* __restrict__ Bh,
                                                const __nv_bfloat16* __restrict__ Bl,
                                                const float* __restrict__ bias,
                                                float* __restrict__ outf,
                                                __nv_bfloat16* __restrict__ outh,
                                                __nv_bfloat16* __restrict__ outl,
                                                int M, int N, int K) {
    extern __shared__ char sm[];
    uint32_t sb = smem_u32(sm);
    int tid  = threadIdx.x;
    int lane = tid & 31;
    int warp = tid >> 5;
    int wm = warp & 3;            // 0..3 (m)
    int wn = warp >> 2;           // 0..1 (n)
    int bm = blockIdx.y * TM;
    int bn = blockIdx.x * TN;

    const __nv_bfloat16* A0h = Ah + (size_t)bm * K;
    const __nv_bfloat16* A0l = Al + (size_t)bm * K;
    const __nv_bfloat16* B0h = Bh + (size_t)bn * K;
    const __nv_bfloat16* B0l = Bl + (size_t)bn * K;

    float acc[2][8][4];
#pragma unroll
    for (int i = 0; i < 2; i++)
#pragma unroll
        for (int j = 0; j < 8; j++)
#pragma unroll
            for (int q = 0; q < 4; q++) acc[i][j][q] = 0.0f;

    int a_row  = wm * 32 + (lane & 15);
    int a_sw   = a_row & 7;
    uint32_t a_off = (uint32_t)a_row * 128;
    int a_kbit = lane >> 4;
    int b_row  = wn * 64 + (lane & 7) + ((lane & 16) ? 8 : 0);
    int b_sw   = b_row & 7;
    uint32_t b_off = (uint32_t)b_row * 128;
    int b_kbit = (lane & 8) ? 1 : 0;

    int NC = K / BK;
    {
        load_tile_ca(A0h, K, 0, sb + 0 * ST_TILE, tid);
        load_tile_ca(A0l, K, 0, sb + 1 * ST_TILE, tid);
        load_tile_ca(B0h, K, 0, sb + 2 * ST_TILE, tid);
        load_tile_ca(B0l, K, 0, sb + 3 * ST_TILE, tid);
        CP_COMMIT();
        load_tile_ca(A0h, K, BK, sb + STAGE + 0 * ST_TILE, tid);
        load_tile_ca(A0l, K, BK, sb + STAGE + 1 * ST_TILE, tid);
        load_tile_ca(B0h, K, BK, sb + STAGE + 2 * ST_TILE, tid);
        load_tile_ca(B0l, K, BK, sb + STAGE + 3 * ST_TILE, tid);
        CP_COMMIT();
    }

    for (int c = 0; c < NC; c++) {
        if (c + 1 < NC) { CP_WAIT(1); } else { CP_WAIT(0); }
        __syncthreads();
        uint32_t base = sb + (uint32_t)(c & 1) * STAGE;
        uint32_t bAh = base + 0 * ST_TILE + a_off;
        uint32_t bAl = base + 1 * ST_TILE + a_off;
        uint32_t bBh = base + 2 * ST_TILE + b_off;
        uint32_t bBl = base + 3 * ST_TILE + b_off;

#pragma unroll
        for (int kk = 0; kk < 4; kk++) {
            uint32_t aun = (uint32_t)(((kk * 2 + a_kbit) ^ a_sw) << 4);
            uint32_t bun = (uint32_t)(((kk * 2 + b_kbit) ^ b_sw) << 4);
            uint32_t ah[2][4], al[2][4];
#pragma unroll
            for (int i = 0; i < 2; i++) {
                ldsm4(bAh + i * 2048 + aun, ah[i][0], ah[i][1], ah[i][2], ah[i][3]);
                ldsm4(bAl + i * 2048 + aun, al[i][0], al[i][1], al[i][2], al[i][3]);
            }
            uint32_t bh[8][2], bl[8][2];
#pragma unroll
            for (int jp = 0; jp < 4; jp++) {
                ldsm4(bBh + jp * 2048 + bun, bh[2 * jp][0], bh[2 * jp][1],
                      bh[2 * jp + 1][0], bh[2 * jp + 1][1]);
                ldsm4(bBl + jp * 2048 + bun, bl[2 * jp][0], bl[2 * jp][1],
                      bl[2 * jp + 1][0], bl[2 * jp + 1][1]);
            }
#pragma unroll
            for (int i = 0; i < 2; i++)
#pragma unroll
                for (int j = 0; j < 8; j++) {
                    mma16816(acc[i][j], ah[i][0], ah[i][1], ah[i][2], ah[i][3],
                             bh[j][0], bh[j][1]);
                    mma16816(acc[i][j], ah[i][0], ah[i][1], ah[i][2], ah[i][3],
                             bl[j][0], bl[j][1]);
                    mma16816(acc[i][j], al[i][0], al[i][1], al[i][2], al[i][3],
                             bh[j][0], bh[j][1]);
                }
        }
        __syncthreads();
        if (c + 2 < NC) {
            uint32_t nb = sb + (uint32_t)(c & 1) * STAGE;
            int k0 = (c + 2) * BK;
            load_tile_ca(A0h, K, k0, nb + 0 * ST_TILE, tid);
            load_tile_ca(A0l, K, k0, nb + 1 * ST_TILE, tid);
            load_tile_ca(B0h, K, k0, nb + 2 * ST_TILE, tid);
            load_tile_ca(B0l, K, k0, nb + 3 * ST_TILE, tid);
            CP_COMMIT();
        }
    }

    int r0g = bm + wm * 32 + (lane >> 2);
    int c0g = bn + wn * 64 + 2 * (lane & 3);
#pragma unroll
    for (int i = 0; i < 2; i++) {
#pragma unroll
        for (int j = 0; j < 8; j++) {
            int r = r0g + i * 16;
            int cc = c0g + j * 8;
            float bz0 = bias[cc], bz1 = bias[cc + 1];
            float v0 = acc[i][j][0] + bz0;
            float v1 = acc[i][j][1] + bz1;
            float v2 = acc[i][j][2] + bz0;
            float v3 = acc[i][j][3] + bz1;
            if (TANH) { v0 = tanhf(v0); v1 = tanhf(v1); v2 = tanhf(v2); v3 = tanhf(v3); }
            if (OUTBF) {
                __nv_bfloat16 h0 = __float2bfloat16_rn(v0);
                __nv_bfloat16 h1 = __float2bfloat16_rn(v1);
                __nv_bfloat16 h2 = __float2bfloat16_rn(v2);
                __nv_bfloat16 h3 = __float2bfloat16_rn(v3);
                uint32_t ph01 = ((uint32_t)__bfloat16_as_ushort(h1) << 16) |
                                (uint32_t)__bfloat16_as_ushort(h0);
                uint32_t ph23 = ((uint32_t)__bfloat16_as_ushort(h3) << 16) |
                                (uint32_t)__bfloat16_as_ushort(h2);
                __nv_bfloat16 l0 = __float2bfloat16_rn(v0 - __bfloat162float(h0));
                __nv_bfloat16 l1 = __float2bfloat16_rn(v1 - __bfloat162float(h1));
                __nv_bfloat16 l2 = __float2bfloat16_rn(v2 - __bfloat162float(h2));
                __nv_bfloat16 l3 = __float2bfloat16_rn(v3 - __bfloat162float(h3));
                uint32_t pl01 = ((uint32_t)__bfloat16_as_ushort(l1) << 16) |
                                (uint32_t)__bfloat16_as_ushort(l0);
                uint32_t pl23 = ((uint32_t)__bfloat16_as_ushort(l3) << 16) |
                                (uint32_t)__bfloat16_as_ushort(l2);
                *(uint32_t*)(outh + (size_t)r * N + cc)       = ph01;
                *(uint32_t*)(outh + (size_t)(r + 8) * N + cc) = ph23;
                *(uint32_t*)(outl + (size_t)r * N + cc)       = pl01;
                *(uint32_t*)(outl + (size_t)(r + 8) * N + cc) = pl23;
            } else {
                *(float2*)(outf + (size_t)r * N + cc)       = make_float2(v0, v1);
                *(float2*)(outf + (size_t)(r + 8) * N + cc) = make_float2(v2, v3);
            }
        }
    }
}

// ---------------- launch ----------------------------------------------------
extern "C" void kernel_launch(void* const* d_in, const int* in_sizes, int n_in,
                              void* d_out, int out_size) {
    const float* u      = (const float*)d_in[0];
    const float* D      = (const float*)d_in[1];
    const float* log_dt = (const float*)d_in[2];
    const float* C_re   = (const float*)d_in[3];
    const float* C_im   = (const float*)d_in[4];
    const float* W1     = (const float*)d_in[5];
    const float* b1     = (const float*)d_in[6];
    const float* W2     = (const float*)d_in[7];
    const float* b2     = (const float*)d_in[8];
    float* out = (float*)d_out;

    float4* modes_p;
    __nv_bfloat16 *yh_p, *yl_p, *w1h_p, *w1l_p, *w2h_p, *w2l_p, *y2h_p, *y2l_p;
    cudaGetSymbolAddress((void**)&modes_p, g_modes);
    cudaGetSymbolAddress((void**)&yh_p,  g_yh);
    cudaGetSymbolAddress((void**)&yl_p,  g_yl);
    cudaGetSymbolAddress((void**)&w1h_p, g_w1h);
    cudaGetSymbolAddress((void**)&w1l_p, g_w1l);
    cudaGetSymbolAddress((void**)&w2h_p, g_w2h);
    cudaGetSymbolAddress((void**)&w2l_p, g_w2l);
    cudaGetSymbolAddress((void**)&y2h_p, g_y2h);
    cudaGetSymbolAddress((void**)&y2l_p, g_y2l);

    cudaFuncSetAttribute(gemm_mma<true, true>,
                         cudaFuncAttributeMaxDynamicSharedMemorySize, GEMM_SMEM);
    cudaFuncSetAttribute(gemm_mma<false, false>,
                         cudaFuncAttributeMaxDynamicSharedMemorySize, GEMM_SMEM);

    setup_modes<<<64, 256>>>(log_dt, C_re, C_im, modes_p);

    transpose_split<<<dim3(1024 / 32, 2048 / 32), dim3(32, 8)>>>(W1, w1h_p, w1l_p,
                                                                 L, 2 * H);
    transpose_split<<<dim3(512 / 32, 1024 / 32), dim3(32, 8)>>>(W2, w2h_p, w2l_p,
                                                                2 * H, H);

    // conv scan: 8192 rows x 8 threads = 65536 threads
    conv_scan<<<(M_TOTAL * 8) / 256, 256>>>(u, D, modes_p, yh_p, yl_p);

    // GEMM1: (8192 x 2048) @ (2048 x 1024) + b1, tanh -> bf16 hi/lo
    gemm_mma<true, true><<<dim3((2 * H) / TN, M_TOTAL / TM), 256, GEMM_SMEM>>>(
        yh_p, yl_p, w1h_p, w1l_p, b1, nullptr, y2h_p, y2l_p,
        M_TOTAL, 2 * H, L);

    // GEMM2: (8192 x 1024) @ (1024 x 512) + b2 -> fp32 out
    gemm_mma<false, false><<<dim3(H / TN, M_TOTAL / TM), 256, GEMM_SMEM>>>(
        y2h_p, y2l_p, w2h_p, w2l_p, b2, out, nullptr, nullptr,
        M_TOTAL, H, 2 * H);
}